// round 3
// baseline (speedup 1.0000x reference)
#include <cuda_runtime.h>
#include <cstdint>
#include <math_constants.h>

// B=32, S=2048, F=512. Output == per-row one-hot of argmax(logits+gumbel):
// straight-through mask is exactly one-hot in fp32, and the top-K zeroing
// only touches entries that are already exactly 0 (see R1 analysis).
//
// R2: pure streaming kernel at the HBM roofline (384 MB irreducible).
// Changes vs R1: fmaxf-based argmax (fma pipe) + REDUX.min index pick
// instead of 64-bit packed-key ALU reduction; streaming .cs cache hints
// (touch-once data). First-occurrence tie-break preserved via min-index.

static constexpr int F_DIM   = 512;
static constexpr int F4      = F_DIM / 4;        // 128 float4 per row
static constexpr int ROWS    = 32 * 2048;        // 65536
static constexpr int WARPS_B = 8;
static constexpr int THREADS = WARPS_B * 32;

__global__ __launch_bounds__(THREADS)
void onehot_argmax_kernel(const float4* __restrict__ logits,
                          const float4* __restrict__ gumbel,
                          float4* __restrict__ out) {
    const int warp = blockIdx.x * WARPS_B + (threadIdx.x >> 5);
    const int lane = threadIdx.x & 31;
    const size_t base = (size_t)warp * F4;

    float s[16];

    // Front-batched, fully coalesced loads (8 LDG.128 per lane, MLP=8).
    #pragma unroll
    for (int it = 0; it < 4; it++) {
        const int off = it * 32 + lane;
        const float4 a = __ldcs(&logits[base + off]);
        const float4 g = __ldcs(&gumbel[base + off]);
        s[it * 4 + 0] = a.x + g.x;
        s[it * 4 + 1] = a.y + g.y;
        s[it * 4 + 2] = a.z + g.z;
        s[it * 4 + 3] = a.w + g.w;
    }

    // Value max: 15 fmaxf (fma pipe) + 5-step butterfly.
    float vmax = s[0];
    #pragma unroll
    for (int i = 1; i < 16; i++) vmax = fmaxf(vmax, s[i]);
    #pragma unroll
    for (int o = 16; o > 0; o >>= 1)
        vmax = fmaxf(vmax, __shfl_xor_sync(0xFFFFFFFFu, vmax, o));

    // Index of FIRST occurrence of vmax (matches jnp argmax tie-break):
    // per-lane min matching index, then warp REDUX.min.
    unsigned cand = 0xFFFFFFFFu;
    #pragma unroll
    for (int it = 0; it < 4; it++) {
        const int e = (it * 32 + lane) * 4;
        #pragma unroll
        for (int c = 0; c < 4; c++) {
            if (s[it * 4 + c] == vmax) cand = min(cand, (unsigned)(e + c));
        }
    }
    const unsigned best = __reduce_min_sync(0xFFFFFFFFu, cand);

    // Coalesced one-hot stores (4 STG.128 per lane), streaming hint.
    #pragma unroll
    for (int it = 0; it < 4; it++) {
        const int off = it * 32 + lane;
        const unsigned e = (unsigned)(off * 4);
        float4 v = make_float4(0.f, 0.f, 0.f, 0.f);
        const unsigned d = best - e;
        if (d < 4u) (&v.x)[d] = 1.0f;
        __stcs(&out[base + off], v);
    }
}

extern "C" void kernel_launch(void* const* d_in, const int* in_sizes, int n_in,
                              void* d_out, int out_size) {
    const float4* logits = (const float4*)d_in[0];
    const float4* gumbel = (const float4*)d_in[1];
    float4* out = (float4*)d_out;

    onehot_argmax_kernel<<<ROWS / WARPS_B, THREADS>>>(logits, gumbel, out);
}

// round 4
// speedup vs baseline: 1.0207x; 1.0207x over previous
#include <cuda_runtime.h>
#include <cstdint>

// B=32, S=2048, F=512. Output == per-row one-hot of argmax(logits+gumbel):
// the straight-through mask is exactly one-hot in fp32, and the top-K
// zeroing only touches entries that are already exactly 0 (R1 analysis).
//
// R3: HBM-roofline streaming kernel (384 MB irreducible traffic).
// vs R2: dropped .cs cache hints (R1's default-cache path measured faster:
// 53.5 vs 55.3 us), kept the cheap fmaxf + REDUX.min reduction, 512-thread
// blocks. Expectation: ~53 us kernel = ~99% of the measured mixed-R/W HBM
// ceiling (6.5 TB/s).

static constexpr int F_DIM   = 512;
static constexpr int F4      = F_DIM / 4;        // 128 float4 per row
static constexpr int ROWS    = 32 * 2048;        // 65536
static constexpr int WARPS_B = 16;               // warps (rows) per block
static constexpr int THREADS = WARPS_B * 32;     // 512

__global__ __launch_bounds__(THREADS)
void onehot_argmax_kernel(const float4* __restrict__ logits,
                          const float4* __restrict__ gumbel,
                          float4* __restrict__ out) {
    const int warp = blockIdx.x * WARPS_B + (threadIdx.x >> 5);
    const int lane = threadIdx.x & 31;
    const size_t base = (size_t)warp * F4;

    float s[16];

    // Front-batched, fully coalesced loads (8 LDG.128 per lane, MLP=8).
    #pragma unroll
    for (int it = 0; it < 4; it++) {
        const int off = it * 32 + lane;
        const float4 a = logits[base + off];
        const float4 g = gumbel[base + off];
        s[it * 4 + 0] = a.x + g.x;
        s[it * 4 + 1] = a.y + g.y;
        s[it * 4 + 2] = a.z + g.z;
        s[it * 4 + 3] = a.w + g.w;
    }

    // Value max: 15 fmaxf (fma pipe) + 5-step butterfly.
    float vmax = s[0];
    #pragma unroll
    for (int i = 1; i < 16; i++) vmax = fmaxf(vmax, s[i]);
    #pragma unroll
    for (int o = 16; o > 0; o >>= 1)
        vmax = fmaxf(vmax, __shfl_xor_sync(0xFFFFFFFFu, vmax, o));

    // Index of FIRST occurrence of vmax (jnp argmax tie-break):
    // per-lane min matching index, then one REDUX.min across the warp.
    unsigned cand = 0xFFFFFFFFu;
    #pragma unroll
    for (int it = 0; it < 4; it++) {
        const int e = (it * 32 + lane) * 4;
        #pragma unroll
        for (int c = 0; c < 4; c++) {
            if (s[it * 4 + c] == vmax) cand = min(cand, (unsigned)(e + c));
        }
    }
    const unsigned best = __reduce_min_sync(0xFFFFFFFFu, cand);

    // Coalesced one-hot stores (4 STG.128 per lane).
    #pragma unroll
    for (int it = 0; it < 4; it++) {
        const int off = it * 32 + lane;
        const unsigned e = (unsigned)(off * 4);
        float4 v = make_float4(0.f, 0.f, 0.f, 0.f);
        const unsigned d = best - e;
        if (d < 4u) (&v.x)[d] = 1.0f;
        out[base + off] = v;
    }
}

extern "C" void kernel_launch(void* const* d_in, const int* in_sizes, int n_in,
                              void* d_out, int out_size) {
    const float4* logits = (const float4*)d_in[0];
    const float4* gumbel = (const float4*)d_in[1];
    float4* out = (float4*)d_out;

    onehot_argmax_kernel<<<ROWS / WARPS_B, THREADS>>>(logits, gumbel, out);
}